// round 1
// baseline (speedup 1.0000x reference)
#include <cuda_runtime.h>
#include <math.h>

#define B_BATCH 512
#define T_SEQ   256
#define C_EMB   384
#define H_DIM   64
#define SCALE   0.125f   // 64^-0.5

// Scratch for Q, K, V: [B*T, H] each = 8,388,608 floats (33.5 MB each)
__device__ float g_Q[B_BATCH * T_SEQ * H_DIM];
__device__ float g_K[B_BATCH * T_SEQ * H_DIM];
__device__ float g_V[B_BATCH * T_SEQ * H_DIM];

// ---------------------------------------------------------------------------
// Kernel 1: fused QKV projection.
// GEMM: [131072 x 384] * [384 x 192]  (cols 0-63 = Q, 64-127 = K, 128-191 = V)
// CTA tile: 64 rows x 192 cols, TK = 16. 256 threads, each 4x12 outputs.
// ---------------------------------------------------------------------------
__global__ __launch_bounds__(256)
void qkv_kernel(const float* __restrict__ x,
                const float* __restrict__ Wq, const float* __restrict__ bq,
                const float* __restrict__ Wk, const float* __restrict__ bk,
                const float* __restrict__ Wv, const float* __restrict__ bv)
{
    __shared__ float As[16][64];    // [k][m]
    __shared__ float Bs[16][192];   // [k][n]

    const int tid = threadIdx.x;          // 0..255
    const int tx  = tid & 15;             // 0..15 -> col group (12 cols)
    const int ty  = tid >> 4;             // 0..15 -> row group (4 rows)
    const int row0 = blockIdx.x * 64;

    // A loader mapping: each thread loads one float4 of x per chunk
    const int a_row = tid >> 2;           // 0..63
    const int a_k4  = (tid & 3) * 4;      // 0,4,8,12

    float acc[4][12];
    #pragma unroll
    for (int r = 0; r < 4; r++)
        #pragma unroll
        for (int c = 0; c < 12; c++)
            acc[r][c] = 0.f;

    for (int k0 = 0; k0 < C_EMB; k0 += 16) {
        // --- load A tile (64 rows x 16 k), transposed into As[k][m] ---
        float4 av = *(const float4*)&x[(size_t)(row0 + a_row) * C_EMB + k0 + a_k4];
        As[a_k4 + 0][a_row] = av.x;
        As[a_k4 + 1][a_row] = av.y;
        As[a_k4 + 2][a_row] = av.z;
        As[a_k4 + 3][a_row] = av.w;

        // --- load B tile (16 k x 192 cols) from Wq|Wk|Wv ---
        #pragma unroll
        for (int i = 0; i < 3; i++) {
            int idx = tid + i * 256;        // float4 index over [16][48]
            int kk  = idx / 48;             // 0..15
            int c4  = (idx % 48) * 4;       // col 0,4,...,188
            const float* Wsrc;
            int wcol;
            if (c4 < 64)       { Wsrc = Wq; wcol = c4; }
            else if (c4 < 128) { Wsrc = Wk; wcol = c4 - 64; }
            else               { Wsrc = Wv; wcol = c4 - 128; }
            float4 bv4 = *(const float4*)&Wsrc[(size_t)(k0 + kk) * H_DIM + wcol];
            *(float4*)&Bs[kk][c4] = bv4;
        }
        __syncthreads();

        // --- compute ---
        #pragma unroll
        for (int k = 0; k < 16; k++) {
            float4 af = *(const float4*)&As[k][ty * 4];
            float a[4] = {af.x, af.y, af.z, af.w};
            float bb[12];
            float4 b0 = *(const float4*)&Bs[k][tx * 12 + 0];
            float4 b1 = *(const float4*)&Bs[k][tx * 12 + 4];
            float4 b2 = *(const float4*)&Bs[k][tx * 12 + 8];
            bb[0]=b0.x; bb[1]=b0.y; bb[2]=b0.z;  bb[3]=b0.w;
            bb[4]=b1.x; bb[5]=b1.y; bb[6]=b1.z;  bb[7]=b1.w;
            bb[8]=b2.x; bb[9]=b2.y; bb[10]=b2.z; bb[11]=b2.w;
            #pragma unroll
            for (int r = 0; r < 4; r++)
                #pragma unroll
                for (int c = 0; c < 12; c++)
                    acc[r][c] = fmaf(a[r], bb[c], acc[r][c]);
        }
        __syncthreads();
    }

    // --- epilogue: add bias, scatter to g_Q / g_K / g_V ---
    #pragma unroll
    for (int r = 0; r < 4; r++) {
        int row = row0 + ty * 4 + r;
        #pragma unroll
        for (int c = 0; c < 12; c++) {
            int col = tx * 12 + c;
            float v = acc[r][c];
            if (col < 64)       g_Q[(size_t)row * H_DIM + col]        = v + bq[col];
            else if (col < 128) g_K[(size_t)row * H_DIM + col - 64]   = v + bk[col - 64];
            else                g_V[(size_t)row * H_DIM + col - 128]  = v + bv[col - 128];
        }
    }
}

// ---------------------------------------------------------------------------
// Kernel 2: causal attention, one CTA per batch element.
// K and V tiles (256 x 64 fp32 each) live in dynamic smem (128 KB).
// One thread per query row; Q row + output accumulator in registers;
// branchless online softmax (always-rescale).
// ---------------------------------------------------------------------------
__global__ __launch_bounds__(256)
void attn_kernel(float* __restrict__ out)
{
    extern __shared__ float sm[];
    float* Ks = sm;                        // [256][64]
    float* Vs = sm + T_SEQ * H_DIM;        // [256][64]

    const int b   = blockIdx.x;
    const int tid = threadIdx.x;           // query row i
    const size_t base = (size_t)b * T_SEQ * H_DIM;

    // cooperative load of K and V (4096 float4 each)
    {
        const float4* Kg4 = (const float4*)(g_K + base);
        const float4* Vg4 = (const float4*)(g_V + base);
        float4* Ks4 = (float4*)Ks;
        float4* Vs4 = (float4*)Vs;
        #pragma unroll
        for (int it = 0; it < 16; it++) {
            int idx = tid + it * 256;
            Ks4[idx] = Kg4[idx];
            Vs4[idx] = Vg4[idx];
        }
    }
    __syncthreads();

    // load this thread's Q row
    float q[H_DIM];
    {
        const float4* Qg4 = (const float4*)(g_Q + base + (size_t)tid * H_DIM);
        #pragma unroll
        for (int h4 = 0; h4 < 16; h4++) {
            float4 v = Qg4[h4];
            q[4*h4+0] = v.x; q[4*h4+1] = v.y; q[4*h4+2] = v.z; q[4*h4+3] = v.w;
        }
    }

    float acc[H_DIM];
    #pragma unroll
    for (int h = 0; h < H_DIM; h++) acc[h] = 0.f;
    float m = -1e30f;
    float l = 0.f;

    const int i = tid;
    for (int j = 0; j <= i; j++) {
        // score
        const float4* kj = (const float4*)(Ks + j * H_DIM);
        float s = 0.f;
        #pragma unroll
        for (int h4 = 0; h4 < 16; h4++) {
            float4 kv = kj[h4];
            s = fmaf(q[4*h4+0], kv.x, s);
            s = fmaf(q[4*h4+1], kv.y, s);
            s = fmaf(q[4*h4+2], kv.z, s);
            s = fmaf(q[4*h4+3], kv.w, s);
        }
        s *= SCALE;

        // online softmax (branchless rescale)
        float mn = fmaxf(m, s);
        float c  = __expf(m - mn);
        float p  = __expf(s - mn);
        l = l * c + p;

        const float4* vj = (const float4*)(Vs + j * H_DIM);
        #pragma unroll
        for (int h4 = 0; h4 < 16; h4++) {
            float4 vv = vj[h4];
            acc[4*h4+0] = fmaf(acc[4*h4+0], c, p * vv.x);
            acc[4*h4+1] = fmaf(acc[4*h4+1], c, p * vv.y);
            acc[4*h4+2] = fmaf(acc[4*h4+2], c, p * vv.z);
            acc[4*h4+3] = fmaf(acc[4*h4+3], c, p * vv.w);
        }
        m = mn;
    }

    const float inv = 1.f / l;
    float4* og = (float4*)(out + base + (size_t)i * H_DIM);
    #pragma unroll
    for (int h4 = 0; h4 < 16; h4++) {
        float4 v;
        v.x = acc[4*h4+0] * inv;
        v.y = acc[4*h4+1] * inv;
        v.z = acc[4*h4+2] * inv;
        v.w = acc[4*h4+3] * inv;
        og[h4] = v;
    }
}

// ---------------------------------------------------------------------------
extern "C" void kernel_launch(void* const* d_in, const int* in_sizes, int n_in,
                              void* d_out, int out_size)
{
    const float* x  = (const float*)d_in[0];
    const float* Wq = (const float*)d_in[1];
    const float* bq = (const float*)d_in[2];
    const float* Wk = (const float*)d_in[3];
    const float* bk = (const float*)d_in[4];
    const float* Wv = (const float*)d_in[5];
    const float* bv = (const float*)d_in[6];
    float* out = (float*)d_out;

    qkv_kernel<<<(B_BATCH * T_SEQ) / 64, 256>>>(x, Wq, bq, Wk, bk, Wv, bv);

    static const int kAttnSmem = 2 * T_SEQ * H_DIM * (int)sizeof(float); // 128 KB
    cudaFuncSetAttribute(attn_kernel, cudaFuncAttributeMaxDynamicSharedMemorySize, kAttnSmem);
    attn_kernel<<<B_BATCH, 256, kAttnSmem>>>(out);
}

// round 3
// speedup vs baseline: 1.1350x; 1.1350x over previous
#include <cuda_runtime.h>
#include <math.h>

#define B_BATCH 512
#define T_SEQ   256
#define C_EMB   384
#define H_DIM   64
#define SCALE   0.125f   // 64^-0.5

typedef unsigned long long u64t;

// Scratch for Q, K, V: [B*T, H] each (33.5 MB each)
__device__ float g_Q[B_BATCH * T_SEQ * H_DIM];
__device__ float g_K[B_BATCH * T_SEQ * H_DIM];
__device__ float g_V[B_BATCH * T_SEQ * H_DIM];

// ---------------- packed f32x2 helpers (Blackwell sm_103a) ----------------
__device__ __forceinline__ u64t f2_pack(float lo, float hi) {
    u64t d;
    asm("mov.b64 %0, {%1, %2};" : "=l"(d) : "f"(lo), "f"(hi));
    return d;
}
__device__ __forceinline__ void f2_unpack(u64t v, float& lo, float& hi) {
    asm("mov.b64 {%0, %1}, %2;" : "=f"(lo), "=f"(hi) : "l"(v));
}
__device__ __forceinline__ u64t f2_fma(u64t a, u64t b, u64t c) {
    u64t d;
    asm("fma.rn.f32x2 %0, %1, %2, %3;" : "=l"(d) : "l"(a), "l"(b), "l"(c));
    return d;
}
__device__ __forceinline__ u64t f2_mul(u64t a, u64t b) {
    u64t d;
    asm("mul.rn.f32x2 %0, %1, %2;" : "=l"(d) : "l"(a), "l"(b));
    return d;
}
__device__ __forceinline__ u64t f2_add(u64t a, u64t b) {
    u64t d;
    asm("add.rn.f32x2 %0, %1, %2;" : "=l"(d) : "l"(a), "l"(b));
    return d;
}

// ---------------------------------------------------------------------------
// Kernel 1: fused QKV projection, packed f32x2 math.
// GEMM: [131072 x 384] * [384 x 192]  (cols 0-63 = Q, 64-127 = K, 128-191 = V)
// CTA tile: 64 rows x 192 cols, TK = 16. 256 threads, each 4 rows x 6 col-pairs.
// ---------------------------------------------------------------------------
__global__ __launch_bounds__(256)
void qkv_kernel(const float* __restrict__ x,
                const float* __restrict__ Wq, const float* __restrict__ bq,
                const float* __restrict__ Wk, const float* __restrict__ bk,
                const float* __restrict__ Wv, const float* __restrict__ bv)
{
    __shared__ __align__(16) float As[16][64];    // [k][m]
    __shared__ __align__(16) float Bs[16][192];   // [k][n]

    const int tid = threadIdx.x;          // 0..255
    const int tx  = tid & 15;             // col group (12 cols = 6 pairs)
    const int ty  = tid >> 4;             // row group (4 rows)
    const int row0 = blockIdx.x * 64;

    const int a_row = tid >> 2;           // 0..63
    const int a_k4  = (tid & 3) * 4;      // 0,4,8,12

    u64t acc[4][6];
    #pragma unroll
    for (int r = 0; r < 4; r++)
        #pragma unroll
        for (int p = 0; p < 6; p++)
            acc[r][p] = f2_pack(0.f, 0.f);

    for (int k0 = 0; k0 < C_EMB; k0 += 16) {
        // --- load A tile (64 rows x 16 k), transposed into As[k][m] ---
        float4 av = *(const float4*)&x[(size_t)(row0 + a_row) * C_EMB + k0 + a_k4];
        As[a_k4 + 0][a_row] = av.x;
        As[a_k4 + 1][a_row] = av.y;
        As[a_k4 + 2][a_row] = av.z;
        As[a_k4 + 3][a_row] = av.w;

        // --- load B tile (16 k x 192 cols) from Wq|Wk|Wv ---
        #pragma unroll
        for (int i = 0; i < 3; i++) {
            int idx = tid + i * 256;        // float4 index over [16][48]
            int kk  = idx / 48;             // 0..15
            int c4  = (idx % 48) * 4;       // col 0,4,...,188
            const float* Wsrc;
            int wcol;
            if (c4 < 64)       { Wsrc = Wq; wcol = c4; }
            else if (c4 < 128) { Wsrc = Wk; wcol = c4 - 64; }
            else               { Wsrc = Wv; wcol = c4 - 128; }
            float4 bv4 = *(const float4*)&Wsrc[(size_t)(k0 + kk) * H_DIM + wcol];
            *(float4*)&Bs[kk][c4] = bv4;
        }
        __syncthreads();

        // --- compute: 24 FFMA2 per k-step ---
        #pragma unroll
        for (int k = 0; k < 16; k++) {
            float4 af = *(const float4*)&As[k][ty * 4];
            u64t a2[4];
            a2[0] = f2_pack(af.x, af.x);
            a2[1] = f2_pack(af.y, af.y);
            a2[2] = f2_pack(af.z, af.z);
            a2[3] = f2_pack(af.w, af.w);
            const u64t* brow = (const u64t*)&Bs[k][tx * 12];
            u64t b2[6];
            #pragma unroll
            for (int p = 0; p < 6; p++) b2[p] = brow[p];
            #pragma unroll
            for (int r = 0; r < 4; r++)
                #pragma unroll
                for (int p = 0; p < 6; p++)
                    acc[r][p] = f2_fma(a2[r], b2[p], acc[r][p]);
        }
        __syncthreads();
    }

    // --- epilogue: add bias, scatter to g_Q / g_K / g_V ---
    #pragma unroll
    for (int r = 0; r < 4; r++) {
        int row = row0 + ty * 4 + r;
        #pragma unroll
        for (int p = 0; p < 6; p++) {
            float v0, v1;
            f2_unpack(acc[r][p], v0, v1);
            #pragma unroll
            for (int e = 0; e < 2; e++) {
                int col = tx * 12 + p * 2 + e;
                float v = (e == 0) ? v0 : v1;
                if (col < 64)       g_Q[(size_t)row * H_DIM + col]        = v + bq[col];
                else if (col < 128) g_K[(size_t)row * H_DIM + col - 64]   = v + bk[col - 64];
                else                g_V[(size_t)row * H_DIM + col - 128]  = v + bv[col - 128];
            }
        }
    }
}

// ---------------------------------------------------------------------------
// Kernel 2: causal attention, one CTA per batch, packed f32x2 math.
// K and V tiles (256 x 64 fp32 each) in dynamic smem (128 KB).
// One thread per query row; online softmax; dot uses 4 packed partials.
// ---------------------------------------------------------------------------
__global__ __launch_bounds__(256)
void attn_kernel(float* __restrict__ out)
{
    extern __shared__ __align__(16) float sm[];
    float* Ks = sm;                        // [256][64]
    float* Vs = sm + T_SEQ * H_DIM;        // [256][64]

    const int b   = blockIdx.x;
    const int tid = threadIdx.x;           // query row i
    const size_t base = (size_t)b * T_SEQ * H_DIM;

    // cooperative load of K and V (4096 float4 each)
    {
        const float4* Kg4 = (const float4*)(g_K + base);
        const float4* Vg4 = (const float4*)(g_V + base);
        float4* Ks4 = (float4*)Ks;
        float4* Vs4 = (float4*)Vs;
        #pragma unroll
        for (int it = 0; it < 16; it++) {
            int idx = tid + it * 256;
            Ks4[idx] = Kg4[idx];
            Vs4[idx] = Vg4[idx];
        }
    }
    __syncthreads();

    // load this thread's Q row as 32 packed pairs
    u64t q2[32];
    {
        const ulonglong2* Qg = (const ulonglong2*)(g_Q + base + (size_t)tid * H_DIM);
        #pragma unroll
        for (int h = 0; h < 16; h++) {
            ulonglong2 v = Qg[h];
            q2[2*h]   = v.x;
            q2[2*h+1] = v.y;
        }
    }

    u64t acc2[32];
    #pragma unroll
    for (int h = 0; h < 32; h++) acc2[h] = f2_pack(0.f, 0.f);
    float m = -1e30f;
    float l = 0.f;

    const int i = tid;
    for (int j = 0; j <= i; j++) {
        // ---- score: 4 independent packed partials ----
        const ulonglong2* kj = (const ulonglong2*)(Ks + j * H_DIM);
        u64t s0 = f2_pack(0.f, 0.f), s1 = s0, s2 = s0, s3 = s0;
        #pragma unroll
        for (int h = 0; h < 16; h += 2) {
            ulonglong2 ka = kj[h];
            ulonglong2 kb = kj[h + 1];
            s0 = f2_fma(q2[2*h],     ka.x, s0);
            s1 = f2_fma(q2[2*h + 1], ka.y, s1);
            s2 = f2_fma(q2[2*h + 2], kb.x, s2);
            s3 = f2_fma(q2[2*h + 3], kb.y, s3);
        }
        u64t sp = f2_add(f2_add(s0, s1), f2_add(s2, s3));
        float slo, shi;
        f2_unpack(sp, slo, shi);
        float s = (slo + shi) * SCALE;

        // ---- online softmax (branchless rescale) ----
        float mn = fmaxf(m, s);
        float c  = __expf(m - mn);
        float p  = __expf(s - mn);
        l = l * c + p;
        m = mn;

        u64t c2 = f2_pack(c, c);
        u64t p2 = f2_pack(p, p);

        // ---- PV update: mul2 + fma2 per pair ----
        const ulonglong2* vj = (const ulonglong2*)(Vs + j * H_DIM);
        #pragma unroll
        for (int h = 0; h < 16; h++) {
            ulonglong2 vv = vj[h];
            acc2[2*h]   = f2_fma(acc2[2*h],   c2, f2_mul(p2, vv.x));
            acc2[2*h+1] = f2_fma(acc2[2*h+1], c2, f2_mul(p2, vv.y));
        }
    }

    const float inv = 1.f / l;
    u64t inv2 = f2_pack(inv, inv);
    ulonglong2* og = (ulonglong2*)(out + base + (size_t)i * H_DIM);
    #pragma unroll
    for (int h = 0; h < 16; h++) {
        ulonglong2 v;
        v.x = f2_mul(acc2[2*h],   inv2);
        v.y = f2_mul(acc2[2*h+1], inv2);
        og[h] = v;
    }
}

// ---------------------------------------------------------------------------
extern "C" void kernel_launch(void* const* d_in, const int* in_sizes, int n_in,
                              void* d_out, int out_size)
{
    const float* x  = (const float*)d_in[0];
    const float* Wq = (const float*)d_in[1];
    const float* bq = (const float*)d_in[2];
    const float* Wk = (const float*)d_in[3];
    const float* bk = (const float*)d_in[4];
    const float* Wv = (const float*)d_in[5];
    const float* bv = (const float*)d_in[6];
    float* out = (float*)d_out;

    qkv_kernel<<<(B_BATCH * T_SEQ) / 64, 256>>>(x, Wq, bq, Wk, bk, Wv, bv);

    static const int kAttnSmem = 2 * T_SEQ * H_DIM * (int)sizeof(float); // 128 KB
    cudaFuncSetAttribute(attn_kernel, cudaFuncAttributeMaxDynamicSharedMemorySize, kAttnSmem);
    attn_kernel<<<B_BATCH, 256, kAttnSmem>>>(out);
}

// round 8
// speedup vs baseline: 1.6038x; 1.4130x over previous
#include <cuda_runtime.h>
#include <cuda_bf16.h>
#include <math.h>
#include <cstdint>

#define B_BATCH 512
#define T_SEQ   256
#define C_EMB   384
#define H_DIM   64
#define SCALE   0.125f   // 64^-0.5

typedef unsigned long long u64t;

// Scratch for Q, K, V: [B*T, H] each (33.5 MB each)
__device__ float g_Q[B_BATCH * T_SEQ * H_DIM];
__device__ float g_K[B_BATCH * T_SEQ * H_DIM];
__device__ float g_V[B_BATCH * T_SEQ * H_DIM];

// Pre-converted weights, transposed: [n=192][k=384] bf16, k contiguous
// (col-major B for mma row.col). hi = bf16(w), lo = bf16(w - hi).
__device__ __align__(16) __nv_bfloat16 g_Bh[192 * 384];
__device__ __align__(16) __nv_bfloat16 g_Bl[192 * 384];

// ---------------- helpers ----------------
__device__ __forceinline__ uint32_t smem_u32(const void* p) {
    uint32_t a;
    asm("{ .reg .u64 t; cvta.to.shared.u64 t, %1; cvt.u32.u64 %0, t; }" : "=r"(a) : "l"(p));
    return a;
}
__device__ __forceinline__ void ldsm4(uint32_t* r, uint32_t addr) {
    asm volatile("ldmatrix.sync.aligned.m8n8.x4.shared.b16 {%0,%1,%2,%3}, [%4];"
        : "=r"(r[0]), "=r"(r[1]), "=r"(r[2]), "=r"(r[3]) : "r"(addr));
}
__device__ __forceinline__ void mma_bf16(float* c, const uint32_t* a, uint32_t b0, uint32_t b1) {
    asm volatile(
        "mma.sync.aligned.m16n8k16.row.col.f32.bf16.bf16.f32 "
        "{%0,%1,%2,%3}, {%4,%5,%6,%7}, {%8,%9}, {%0,%1,%2,%3};"
        : "+f"(c[0]), "+f"(c[1]), "+f"(c[2]), "+f"(c[3])
        : "r"(a[0]), "r"(a[1]), "r"(a[2]), "r"(a[3]), "r"(b0), "r"(b1));
}

// packed f32x2 helpers (attn kernel)
__device__ __forceinline__ u64t f2_pack(float lo, float hi) {
    u64t d; asm("mov.b64 %0, {%1, %2};" : "=l"(d) : "f"(lo), "f"(hi)); return d;
}
__device__ __forceinline__ void f2_unpack(u64t v, float& lo, float& hi) {
    asm("mov.b64 {%0, %1}, %2;" : "=f"(lo), "=f"(hi) : "l"(v));
}
__device__ __forceinline__ u64t f2_fma(u64t a, u64t b, u64t c) {
    u64t d; asm("fma.rn.f32x2 %0, %1, %2, %3;" : "=l"(d) : "l"(a), "l"(b), "l"(c)); return d;
}
__device__ __forceinline__ u64t f2_mul(u64t a, u64t b) {
    u64t d; asm("mul.rn.f32x2 %0, %1, %2;" : "=l"(d) : "l"(a), "l"(b)); return d;
}
__device__ __forceinline__ u64t f2_add(u64t a, u64t b) {
    u64t d; asm("add.rn.f32x2 %0, %1, %2;" : "=l"(d) : "l"(a), "l"(b)); return d;
}

// ---------------------------------------------------------------------------
// Setup: transpose+split weights into g_Bh / g_Bl  [n=192][k=384]
// n<64 -> Wq col n ; n<128 -> Wk ; else Wv. W layout is [k=384][h=64].
// ---------------------------------------------------------------------------
__global__ void setup_b_kernel(const float* __restrict__ Wq,
                               const float* __restrict__ Wk,
                               const float* __restrict__ Wv)
{
    int idx = blockIdx.x * blockDim.x + threadIdx.x;   // 73728 total
    if (idx >= 192 * 384) return;
    int n = idx / 384;
    int k = idx % 384;
    float v;
    if (n < 64)        v = Wq[k * H_DIM + n];
    else if (n < 128)  v = Wk[k * H_DIM + (n - 64)];
    else               v = Wv[k * H_DIM + (n - 128)];
    __nv_bfloat16 hi = __float2bfloat16_rn(v);
    float hf = __bfloat162float(hi);
    __nv_bfloat16 lo = __float2bfloat16_rn(v - hf);
    g_Bh[idx] = hi;
    g_Bl[idx] = lo;
}

// ---------------------------------------------------------------------------
// Kernel 1: QKV projection via mma.sync bf16 (3-term split, fp32 accum).
// CTA: 128 rows x 192 cols; K = 384 in 12 chunks of 32.
// 8 warps: wm = wid&3 (M 32-row band), wn = wid>>2 (N 96-col band).
// smem rows padded to 40 halves (80B) -> conflict-free ldmatrix.
// ---------------------------------------------------------------------------
#define KC       32          // k per chunk
#define NCHUNK   12
#define ROWP     40          // padded row stride in halves
// smem layout (halves): Ah[128*40] Al[128*40] Bh[192*40] Bl[192*40], bias after
#define OFF_AH   0
#define OFF_AL   (128 * ROWP)
#define OFF_BH   (2 * 128 * ROWP)
#define OFF_BL   (2 * 128 * ROWP + 192 * ROWP)
#define HALVES_TOTAL (2 * 128 * ROWP + 2 * 192 * ROWP)   // 25600
#define QKV_SMEM (HALVES_TOTAL * 2 + 192 * 4)            // 51968 bytes

__global__ __launch_bounds__(256)
void qkv_mma_kernel(const float* __restrict__ x,
                    const float* __restrict__ bq,
                    const float* __restrict__ bk,
                    const float* __restrict__ bv)
{
    extern __shared__ __align__(16) __nv_bfloat16 sm[];
    float* sbias = (float*)(sm + HALVES_TOTAL);
    const uint32_t sbase = smem_u32(sm);

    const int tid  = threadIdx.x;
    const int lane = tid & 31;
    const int wid  = tid >> 5;
    const int wm   = wid & 3;       // M band: rows wm*32 .. +31
    const int wn   = wid >> 2;      // N band: cols wn*96 .. +95
    const int row0 = blockIdx.x * 128;

    if (tid < 192) {
        sbias[tid] = (tid < 64) ? bq[tid] : (tid < 128) ? bk[tid - 64] : bv[tid - 128];
    }

    // ldmatrix lane address components
    // A (row-major m x k): lanes 0-15 rows, 16-31 rows with k+8
    const int a_row = wm * 32 + (lane & 15);
    const int a_kof = (lane >> 4) << 3;
    // B (col-major via [n][k] rows): mats (n0-7,k0)(n0-7,k8)(n8-15,k0)(n8-15,k8)
    const int b_nrow = ((lane >> 4) << 3) + (lane & 7);
    const int b_kof  = ((lane >> 3) & 1) << 3;

    uint32_t aAddrH[2], aAddrL[2];        // per m16 tile
    #pragma unroll
    for (int tm = 0; tm < 2; tm++) {
        int r = a_row + tm * 16;
        aAddrH[tm] = sbase + (uint32_t)((OFF_AH + r * ROWP + a_kof) * 2);
        aAddrL[tm] = sbase + (uint32_t)((OFF_AL + r * ROWP + a_kof) * 2);
    }
    uint32_t bAddrH[6], bAddrL[6];        // per n16 group
    #pragma unroll
    for (int g6 = 0; g6 < 6; g6++) {
        int n = wn * 96 + g6 * 16 + b_nrow;
        bAddrH[g6] = sbase + (uint32_t)((OFF_BH + n * ROWP + b_kof) * 2);
        bAddrL[g6] = sbase + (uint32_t)((OFF_BL + n * ROWP + b_kof) * 2);
    }

    float acc[2][12][4];
    #pragma unroll
    for (int tm = 0; tm < 2; tm++)
        #pragma unroll
        for (int nt = 0; nt < 12; nt++)
            #pragma unroll
            for (int e = 0; e < 4; e++) acc[tm][nt][e] = 0.f;

    for (int cc = 0; cc < NCHUNK; cc++) {
        // ---- stage A chunk: 128 rows x 32 fp32 -> bf16 hi/lo ----
        #pragma unroll
        for (int i = 0; i < 4; i++) {
            int idx = tid + i * 256;          // 1024 float4 total
            int r = idx >> 3;
            int q = idx & 7;
            float4 v = *(const float4*)&x[(size_t)(row0 + r) * C_EMB + cc * KC + q * 4];
            uint32_t hp0, hp1, lp0, lp1;
            asm("cvt.rn.bf16x2.f32 %0, %1, %2;" : "=r"(hp0) : "f"(v.y), "f"(v.x));
            asm("cvt.rn.bf16x2.f32 %0, %1, %2;" : "=r"(hp1) : "f"(v.w), "f"(v.z));
            float h0 = __uint_as_float(hp0 << 16);
            float h1 = __uint_as_float(hp0 & 0xFFFF0000u);
            float h2 = __uint_as_float(hp1 << 16);
            float h3 = __uint_as_float(hp1 & 0xFFFF0000u);
            asm("cvt.rn.bf16x2.f32 %0, %1, %2;" : "=r"(lp0) : "f"(v.y - h1), "f"(v.x - h0));
            asm("cvt.rn.bf16x2.f32 %0, %1, %2;" : "=r"(lp1) : "f"(v.w - h3), "f"(v.z - h2));
            uint32_t* dh = (uint32_t*)(sm + OFF_AH + r * ROWP + q * 4);
            uint32_t* dl = (uint32_t*)(sm + OFF_AL + r * ROWP + q * 4);
            dh[0] = hp0; dh[1] = hp1;
            dl[0] = lp0; dl[1] = lp1;
        }
        // ---- stage B chunk: 192 rows x 32 halves, hi + lo ----
        #pragma unroll
        for (int i = 0; i < 6; i++) {
            int idx = tid + i * 256;          // 1536 uint2 per term
            int n = idx >> 3;
            int j = idx & 7;
            uint2 vh = *(const uint2*)(g_Bh + n * C_EMB + cc * KC + j * 4);
            uint2 vl = *(const uint2*)(g_Bl + n * C_EMB + cc * KC + j * 4);
            *(uint2*)(sm + OFF_BH + n * ROWP + j * 4) = vh;
            *(uint2*)(sm + OFF_BL + n * ROWP + j * 4) = vl;
        }
        __syncthreads();

        // ---- compute: 2 k-steps of 16 ----
        #pragma unroll
        for (int ks = 0; ks < 2; ks++) {
            const uint32_t kb = (uint32_t)(ks * 32);   // 16 halves
            uint32_t ah[2][4], al[2][4];
            ldsm4(ah[0], aAddrH[0] + kb);
            ldsm4(ah[1], aAddrH[1] + kb);
            ldsm4(al[0], aAddrL[0] + kb);
            ldsm4(al[1], aAddrL[1] + kb);
            #pragma unroll
            for (int g6 = 0; g6 < 6; g6++) {
                uint32_t bh[4], bl[4];
                ldsm4(bh, bAddrH[g6] + kb);
                ldsm4(bl, bAddrL[g6] + kb);
                #pragma unroll
                for (int tm = 0; tm < 2; tm++) {
                    #pragma unroll
                    for (int h = 0; h < 2; h++) {
                        float* c = acc[tm][g6 * 2 + h];
                        mma_bf16(c, ah[tm], bh[2 * h], bh[2 * h + 1]);
                        mma_bf16(c, ah[tm], bl[2 * h], bl[2 * h + 1]);
                        mma_bf16(c, al[tm], bh[2 * h], bh[2 * h + 1]);
                    }
                }
            }
        }
        __syncthreads();
    }

    // ---- epilogue: bias + scatter to g_Q / g_K / g_V ----
    const int g   = lane >> 2;
    const int tig = lane & 3;
    float* outs[3] = { g_Q, g_K, g_V };
    #pragma unroll
    for (int tm = 0; tm < 2; tm++) {
        int rowA = row0 + wm * 32 + tm * 16 + g;
        int rowB = rowA + 8;
        #pragma unroll
        for (int nt = 0; nt < 12; nt++) {
            int gcol = wn * 96 + nt * 8 + 2 * tig;
            int seg  = gcol >> 6;
            int lcol = gcol & 63;
            float b0v = sbias[gcol], b1v = sbias[gcol + 1];
            float2 vA = { acc[tm][nt][0] + b0v, acc[tm][nt][1] + b1v };
            float2 vB = { acc[tm][nt][2] + b0v, acc[tm][nt][3] + b1v };
            *(float2*)(outs[seg] + (size_t)rowA * H_DIM + lcol) = vA;
            *(float2*)(outs[seg] + (size_t)rowB * H_DIM + lcol) = vB;
        }
    }
}

// ---------------------------------------------------------------------------
// Kernel 2: causal attention (packed f32x2, unchanged).
// ---------------------------------------------------------------------------
__global__ __launch_bounds__(256)
void attn_kernel(float* __restrict__ out)
{
    extern __shared__ __align__(16) float smf[];
    float* Ks = smf;
    float* Vs = smf + T_SEQ * H_DIM;

    const int b   = blockIdx.x;
    const int tid = threadIdx.x;
    const size_t base = (size_t)b * T_SEQ * H_DIM;

    {
        const float4* Kg4 = (const float4*)(g_K + base);
        const float4* Vg4 = (const float4*)(g_V + base);
        float4* Ks4 = (float4*)Ks;
        float4* Vs4 = (float4*)Vs;
        #pragma unroll
        for (int it = 0; it < 16; it++) {
            int idx = tid + it * 256;
            Ks4[idx] = Kg4[idx];
            Vs4[idx] = Vg4[idx];
        }
    }
    __syncthreads();

    u64t q2[32];
    {
        const ulonglong2* Qg = (const ulonglong2*)(g_Q + base + (size_t)tid * H_DIM);
        #pragma unroll
        for (int h = 0; h < 16; h++) {
            ulonglong2 v = Qg[h];
            q2[2 * h] = v.x;
            q2[2 * h + 1] = v.y;
        }
    }

    u64t acc2[32];
    #pragma unroll
    for (int h = 0; h < 32; h++) acc2[h] = f2_pack(0.f, 0.f);
    float m = -1e30f;
    float l = 0.f;

    const int i = tid;
    for (int j = 0; j <= i; j++) {
        const ulonglong2* kj = (const ulonglong2*)(Ks + j * H_DIM);
        u64t s0 = f2_pack(0.f, 0.f), s1 = s0, s2 = s0, s3 = s0;
        #pragma unroll
        for (int h = 0; h < 16; h += 2) {
            ulonglong2 ka = kj[h];
            ulonglong2 kb = kj[h + 1];
            s0 = f2_fma(q2[2 * h],     ka.x, s0);
            s1 = f2_fma(q2[2 * h + 1], ka.y, s1);
            s2 = f2_fma(q2[2 * h + 2], kb.x, s2);
            s3 = f2_fma(q2[2 * h + 3], kb.y, s3);
        }
        u64t sp = f2_add(f2_add(s0, s1), f2_add(s2, s3));
        float slo, shi;
        f2_unpack(sp, slo, shi);
        float s = (slo + shi) * SCALE;

        float mn = fmaxf(m, s);
        float c  = __expf(m - mn);
        float p  = __expf(s - mn);
        l = l * c + p;
        m = mn;

        u64t c2 = f2_pack(c, c);
        u64t p2 = f2_pack(p, p);

        const ulonglong2* vj = (const ulonglong2*)(Vs + j * H_DIM);
        #pragma unroll
        for (int h = 0; h < 16; h++) {
            ulonglong2 vv = vj[h];
            acc2[2 * h]     = f2_fma(acc2[2 * h],     c2, f2_mul(p2, vv.x));
            acc2[2 * h + 1] = f2_fma(acc2[2 * h + 1], c2, f2_mul(p2, vv.y));
        }
    }

    const float inv = 1.f / l;
    u64t inv2 = f2_pack(inv, inv);
    ulonglong2* og = (ulonglong2*)(out + base + (size_t)i * H_DIM);
    #pragma unroll
    for (int h = 0; h < 16; h++) {
        ulonglong2 v;
        v.x = f2_mul(acc2[2 * h],     inv2);
        v.y = f2_mul(acc2[2 * h + 1], inv2);
        og[h] = v;
    }
}

// ---------------------------------------------------------------------------
extern "C" void kernel_launch(void* const* d_in, const int* in_sizes, int n_in,
                              void* d_out, int out_size)
{
    const float* x  = (const float*)d_in[0];
    const float* Wq = (const float*)d_in[1];
    const float* bq = (const float*)d_in[2];
    const float* Wk = (const float*)d_in[3];
    const float* bk = (const float*)d_in[4];
    const float* Wv = (const float*)d_in[5];
    const float* bv = (const float*)d_in[6];
    float* out = (float*)d_out;

    setup_b_kernel<<<288, 256>>>(Wq, Wk, Wv);

    cudaFuncSetAttribute(qkv_mma_kernel, cudaFuncAttributeMaxDynamicSharedMemorySize, QKV_SMEM);
    qkv_mma_kernel<<<(B_BATCH * T_SEQ) / 128, 256, QKV_SMEM>>>(x, bq, bk, bv);

    static const int kAttnSmem = 2 * T_SEQ * H_DIM * (int)sizeof(float); // 128 KB
    cudaFuncSetAttribute(attn_kernel, cudaFuncAttributeMaxDynamicSharedMemorySize, kAttnSmem);
    attn_kernel<<<B_BATCH, 256, kAttnSmem>>>(out);
}